// round 2
// baseline (speedup 1.0000x reference)
#include <cuda_runtime.h>
#include <math.h>

#define N_NODES 100000
#define N_EDGES 1600000
#define HC      128
#define INC     128
#define EDIM    16

// ---------------- scratch (device globals: no allocation allowed) ----------------
__device__ float g_q[(size_t)N_NODES * HC];
__device__ float g_k[(size_t)N_NODES * HC];
__device__ float g_v[(size_t)N_NODES * HC];
__device__ float g_skip[(size_t)N_NODES * HC];
__device__ int   g_deg[N_NODES];
__device__ int   g_off[N_NODES + 1];
__device__ int   g_cur[N_NODES];
__device__ int   g_ssrc[N_EDGES];
__device__ int   g_seid[N_EDGES];

// ---------------- kernel 0: zero degree histogram ----------------
__global__ void zero_deg_kernel(int n) {
    int i = blockIdx.x * blockDim.x + threadIdx.x;
    if (i < n) g_deg[i] = 0;
}

// ---------------- kernel 1: fused 4-way GEMM  Y = X @ W + b ----------------
// BM=128, BN=128 (full out width), BK=16, 256 threads, 8x8 microtile.
// blockIdx.z selects (W, b, Y) among {q, k, v, skip}.
__global__ __launch_bounds__(256)
void gemm4_kernel(const float* __restrict__ x,
                  const float* __restrict__ Wq, const float* __restrict__ bq,
                  const float* __restrict__ Wk, const float* __restrict__ bk,
                  const float* __restrict__ Wv, const float* __restrict__ bv,
                  const float* __restrict__ Ws, const float* __restrict__ bs,
                  int n)
{
    const float* W; const float* bias; float* Y;
    switch (blockIdx.z) {
        case 0:  W = Wq; bias = bq; Y = g_q;    break;
        case 1:  W = Wk; bias = bk; Y = g_k;    break;
        case 2:  W = Wv; bias = bv; Y = g_v;    break;
        default: W = Ws; bias = bs; Y = g_skip; break;
    }

    __shared__ float As[16][128];   // [k][row]
    __shared__ float Bs[16][128];   // [k][col]

    const int tid = threadIdx.x;
    const int tx  = tid & 15;       // col group: cols tx*8 .. tx*8+7
    const int ty  = tid >> 4;       // row group: rows ty*8 .. ty*8+7
    const int row0 = blockIdx.x * 128;

    float acc[8][8];
    #pragma unroll
    for (int i = 0; i < 8; i++)
        #pragma unroll
        for (int j = 0; j < 8; j++) acc[i][j] = 0.f;

    for (int k0 = 0; k0 < INC; k0 += 16) {
        // load A tile (128 rows x 16 k), transposed into As[k][row]
        #pragma unroll
        for (int it = 0; it < 2; it++) {
            int f  = tid + it * 256;        // 0..511 float4 slots
            int r  = f & 127;
            int q4 = (f >> 7) * 4;          // 0,4,8,12
            int grow = row0 + r;
            float4 a4 = make_float4(0.f, 0.f, 0.f, 0.f);
            if (grow < n)
                a4 = *(const float4*)(x + (size_t)grow * INC + k0 + q4);
            As[q4 + 0][r] = a4.x;
            As[q4 + 1][r] = a4.y;
            As[q4 + 2][r] = a4.z;
            As[q4 + 3][r] = a4.w;
        }
        // load B tile (16 k x 128 cols)
        #pragma unroll
        for (int it = 0; it < 2; it++) {
            int f  = tid + it * 256;        // 0..511 float4 slots
            int kk = f >> 5;
            int c4 = (f & 31) * 4;
            *(float4*)&Bs[kk][c4] =
                *(const float4*)(W + (size_t)(k0 + kk) * HC + c4);
        }
        __syncthreads();

        #pragma unroll
        for (int kk = 0; kk < 16; kk++) {
            float4 a0 = *(const float4*)&As[kk][ty * 8];
            float4 a1 = *(const float4*)&As[kk][ty * 8 + 4];
            float4 b0 = *(const float4*)&Bs[kk][tx * 8];
            float4 b1 = *(const float4*)&Bs[kk][tx * 8 + 4];
            float a[8] = {a0.x, a0.y, a0.z, a0.w, a1.x, a1.y, a1.z, a1.w};
            float b[8] = {b0.x, b0.y, b0.z, b0.w, b1.x, b1.y, b1.z, b1.w};
            #pragma unroll
            for (int i = 0; i < 8; i++)
                #pragma unroll
                for (int j = 0; j < 8; j++)
                    acc[i][j] += a[i] * b[j];
        }
        __syncthreads();
    }

    float4 bv0 = *(const float4*)(bias + tx * 8);
    float4 bv1 = *(const float4*)(bias + tx * 8 + 4);
    #pragma unroll
    for (int i = 0; i < 8; i++) {
        int grow = row0 + ty * 8 + i;
        if (grow < n) {
            float4 o0, o1;
            o0.x = acc[i][0] + bv0.x; o0.y = acc[i][1] + bv0.y;
            o0.z = acc[i][2] + bv0.z; o0.w = acc[i][3] + bv0.w;
            o1.x = acc[i][4] + bv1.x; o1.y = acc[i][5] + bv1.y;
            o1.z = acc[i][6] + bv1.z; o1.w = acc[i][7] + bv1.w;
            *(float4*)(Y + (size_t)grow * HC + tx * 8)     = o0;
            *(float4*)(Y + (size_t)grow * HC + tx * 8 + 4) = o1;
        }
    }
}

// ---------------- kernel 2: degree histogram ----------------
__global__ void hist_kernel(const int* __restrict__ row, int e) {
    int i = blockIdx.x * blockDim.x + threadIdx.x;
    if (i < e) atomicAdd(&g_deg[row[i]], 1);
}

// ---------------- kernel 3: single-block exclusive scan ----------------
__global__ void scan_kernel(int n, int e) {
    __shared__ int part[1024];
    const int tid = threadIdx.x;
    const int chunk = (n + 1023) / 1024;
    const int s = tid * chunk;
    const int lim = min(s + chunk, n);

    int sum = 0;
    for (int i = s; i < lim; i++) sum += g_deg[i];
    part[tid] = sum;
    __syncthreads();

    // Hillis-Steele inclusive scan (read-all, sync, write, sync)
    for (int off = 1; off < 1024; off <<= 1) {
        int v = part[tid];
        int add = (tid >= off) ? part[tid - off] : 0;
        __syncthreads();
        part[tid] = v + add;
        __syncthreads();
    }

    int run = (tid > 0) ? part[tid - 1] : 0;
    for (int i = s; i < lim; i++) {
        int d = g_deg[i];
        g_off[i] = run;
        g_cur[i] = run;
        run += d;
    }
    if (tid == 1023) g_off[n] = e;
}

// ---------------- kernel 4: scatter edges into CSR ----------------
__global__ void scatter_kernel(const int* __restrict__ row,
                               const int* __restrict__ col, int e) {
    int i = blockIdx.x * blockDim.x + threadIdx.x;
    if (i < e) {
        int d = row[i];
        int p = atomicAdd(&g_cur[d], 1);
        g_ssrc[p] = col[i];
        g_seid[p] = i;
    }
}

// ---------------- kernel 5: per-node attention aggregation + gated skip ----------------
// One warp per destination node. 8 warps / block.
// out = (sum_e exp(logit_e) * v_e) / (sum_e exp(logit_e)); logit uses the
// identity q.(edge_attr@We) = edge_attr.(We^T q), precomputed per node.
__global__ __launch_bounds__(256)
void agg_kernel(const float* __restrict__ edge_attr,
                const float* __restrict__ We,
                const float* __restrict__ Wbeta,
                float* __restrict__ out, int n)
{
    __shared__ __align__(16) float4 sWe[EDIM][32];     // We[d][4l..4l+3]
    __shared__ __align__(16) float swa[HC];            // Wbeta[c] + Wbeta[2HC+c]
    __shared__ __align__(16) float swb[HC];            // Wbeta[HC+c] - Wbeta[2HC+c]

    const int tid = threadIdx.x;
    for (int f = tid; f < EDIM * 32; f += blockDim.x) {
        int d = f >> 5, l = f & 31;
        sWe[d][l] = *(const float4*)(We + (size_t)d * HC + l * 4);
    }
    for (int c = tid; c < HC; c += blockDim.x) {
        float w0 = Wbeta[c], w1 = Wbeta[HC + c], w2 = Wbeta[2 * HC + c];
        swa[c] = w0 + w2;
        swb[c] = w1 - w2;
    }
    __syncthreads();

    const int warp = tid >> 5;
    const int lane = tid & 31;
    const int node = blockIdx.x * (blockDim.x >> 5) + warp;
    if (node >= n) return;

    const float scale = 0.17677669529663687f;  // 1/sqrt(32)
    float4 q4 = *(const float4*)(g_q + (size_t)node * HC + lane * 4);
    q4.x *= scale; q4.y *= scale; q4.z *= scale; q4.w *= scale;

    // per-node projection t[d] = sum_c q_scaled[h,c] * We[d, h*32+c],
    // distributed: this lane holds t for d0 = 2*(lane&7), d1 = d0+1 of its head.
    float t0 = 0.f, t1 = 0.f;
    {
        float pd[EDIM];
        #pragma unroll
        for (int d = 0; d < EDIM; d++) {
            float4 w = sWe[d][lane];
            pd[d] = q4.x * w.x + q4.y * w.y + q4.z * w.z + q4.w * w.w;
        }
        #pragma unroll
        for (int d = 0; d < EDIM; d++) {
            float s = pd[d];
            s += __shfl_xor_sync(0xffffffffu, s, 1);
            s += __shfl_xor_sync(0xffffffffu, s, 2);
            s += __shfl_xor_sync(0xffffffffu, s, 4);
            if ((lane & 7) == (d >> 1)) {
                if (d & 1) t1 = s; else t0 = s;
            }
        }
    }

    const int start = g_off[node];
    const int end   = g_off[node + 1];
    const int dsel  = 2 * (lane & 7);

    float4 acc = make_float4(0.f, 0.f, 0.f, 0.f);
    float  den = 0.f;

    for (int base = start; base < end; base += 32) {
        int idx = base + lane;
        int s_l = 0, e_l = 0;
        if (idx < end) { s_l = g_ssrc[idx]; e_l = g_seid[idx]; }
        int cnt = min(32, end - base);
        for (int j = 0; j < cnt; j++) {
            int src = __shfl_sync(0xffffffffu, s_l, j);
            int eid = __shfl_sync(0xffffffffu, e_l, j);

            float4 kv = __ldg((const float4*)(g_k + (size_t)src * HC + lane * 4));
            float4 vv = __ldg((const float4*)(g_v + (size_t)src * HC + lane * 4));
            float2 ea = __ldg((const float2*)(edge_attr + (size_t)eid * EDIM + dsel));

            float p = q4.x * kv.x + q4.y * kv.y + q4.z * kv.z + q4.w * kv.w
                    + ea.x * t0 + ea.y * t1;
            p += __shfl_xor_sync(0xffffffffu, p, 1);
            p += __shfl_xor_sync(0xffffffffu, p, 2);
            p += __shfl_xor_sync(0xffffffffu, p, 4);

            float ex = __expf(p);
            den += ex;
            acc.x += ex * vv.x; acc.y += ex * vv.y;
            acc.z += ex * vv.z; acc.w += ex * vv.w;
        }
    }

    float inv = 1.f / (den + 1e-16f);
    float4 o = make_float4(acc.x * inv, acc.y * inv, acc.z * inv, acc.w * inv);
    float4 sk = *(const float4*)(g_skip + (size_t)node * HC + lane * 4);
    float4 wa = *(const float4*)(swa + lane * 4);
    float4 wb = *(const float4*)(swb + lane * 4);

    float s = o.x * wa.x + o.y * wa.y + o.z * wa.z + o.w * wa.w
            + sk.x * wb.x + sk.y * wb.y + sk.z * wb.z + sk.w * wb.w;
    #pragma unroll
    for (int off = 16; off; off >>= 1)
        s += __shfl_xor_sync(0xffffffffu, s, off);

    float beta = 1.f / (1.f + __expf(-s));
    float4 r;
    r.x = beta * sk.x + (1.f - beta) * o.x;
    r.y = beta * sk.y + (1.f - beta) * o.y;
    r.z = beta * sk.z + (1.f - beta) * o.z;
    r.w = beta * sk.w + (1.f - beta) * o.w;
    *(float4*)(out + (size_t)node * HC + lane * 4) = r;
}

// ---------------- launch ----------------
extern "C" void kernel_launch(void* const* d_in, const int* in_sizes, int n_in,
                              void* d_out, int out_size)
{
    const float* x         = (const float*)d_in[0];
    const float* edge_attr = (const float*)d_in[1];
    const int*   eidx      = (const int*)  d_in[2];
    const float* Wq = (const float*)d_in[3];
    const float* bq = (const float*)d_in[4];
    const float* Wk = (const float*)d_in[5];
    const float* bk = (const float*)d_in[6];
    const float* Wv = (const float*)d_in[7];
    const float* bv = (const float*)d_in[8];
    const float* We = (const float*)d_in[9];
    const float* Ws = (const float*)d_in[10];
    const float* bs = (const float*)d_in[11];
    const float* Wb = (const float*)d_in[12];
    float* out = (float*)d_out;

    const int n = in_sizes[0] / INC;        // 100000
    const int e = in_sizes[2] / 2;          // 1600000
    const int* row = eidx;                  // dst
    const int* col = eidx + e;              // src

    zero_deg_kernel<<<(n + 255) / 256, 256>>>(n);

    dim3 ggrid((n + 127) / 128, 1, 4);
    gemm4_kernel<<<ggrid, 256>>>(x, Wq, bq, Wk, bk, Wv, bv, Ws, bs, n);

    hist_kernel<<<(e + 255) / 256, 256>>>(row, e);
    scan_kernel<<<1, 1024>>>(n, e);
    scatter_kernel<<<(e + 255) / 256, 256>>>(row, col, e);

    agg_kernel<<<(n + 7) / 8, 256>>>(edge_attr, We, Wb, out, n);
}

// round 3
// speedup vs baseline: 1.2141x; 1.2141x over previous
#include <cuda_runtime.h>
#include <math.h>

#define N_NODES 100000
#define N_EDGES 1600000
#define HC      128
#define INC     128
#define EDIM    16

typedef unsigned long long u64;

// ---------------- scratch (device globals: no allocation allowed) ----------------
__device__ float g_q[(size_t)N_NODES * HC];
__device__ float g_k[(size_t)N_NODES * HC];
__device__ float g_v[(size_t)N_NODES * HC];
__device__ float g_skip[(size_t)N_NODES * HC];
__device__ int   g_deg[N_NODES];
__device__ int   g_off[N_NODES + 1];
__device__ int   g_cur[N_NODES];
__device__ int   g_ssrc[N_EDGES];
__device__ int   g_seid[N_EDGES];
__device__ int   g_bsum[256];
__device__ int   g_bbase[256];

// ---------------- packed f32x2 helpers (sm_103a FFMA2 path) ----------------
__device__ __forceinline__ u64 pack_dup(float a) {
    u64 r; asm("mov.b64 %0, {%1, %1};" : "=l"(r) : "f"(a)); return r;
}
__device__ __forceinline__ u64 pack2(float lo, float hi) {
    u64 r; asm("mov.b64 %0, {%1, %2};" : "=l"(r) : "f"(lo), "f"(hi)); return r;
}
__device__ __forceinline__ u64 ffma2(u64 a, u64 b, u64 c) {
    u64 d; asm("fma.rn.f32x2 %0, %1, %2, %3;" : "=l"(d) : "l"(a), "l"(b), "l"(c));
    return d;
}
__device__ __forceinline__ float2 unpack2(u64 v) {
    float lo, hi; asm("mov.b64 {%0, %1}, %2;" : "=f"(lo), "=f"(hi) : "l"(v));
    return make_float2(lo, hi);
}

// ---------------- kernel 0: zero degree histogram ----------------
__global__ void zero_deg_kernel(int n) {
    int i = blockIdx.x * blockDim.x + threadIdx.x;
    if (i < n) g_deg[i] = 0;
}

// ---------------- kernel 1: fused 4-way GEMM  Y = X @ W + b (FFMA2) ----------------
// BM=128, BN=128, BK=16, 256 threads, 8x8 microtile with packed f32x2 accum.
__global__ __launch_bounds__(256)
void gemm4_kernel(const float* __restrict__ x,
                  const float* __restrict__ Wq, const float* __restrict__ bq,
                  const float* __restrict__ Wk, const float* __restrict__ bk,
                  const float* __restrict__ Wv, const float* __restrict__ bv,
                  const float* __restrict__ Ws, const float* __restrict__ bs,
                  int n)
{
    const float* W; const float* bias; float* Y;
    switch (blockIdx.z) {
        case 0:  W = Wq; bias = bq; Y = g_q;    break;
        case 1:  W = Wk; bias = bk; Y = g_k;    break;
        case 2:  W = Wv; bias = bv; Y = g_v;    break;
        default: W = Ws; bias = bs; Y = g_skip; break;
    }

    __shared__ float As[16][128];   // [k][row]
    __shared__ float Bs[16][128];   // [k][col]

    const int tid = threadIdx.x;
    const int tx  = tid & 15;       // col group: cols tx*8 .. tx*8+7
    const int ty  = tid >> 4;       // row group: rows ty*8 .. ty*8+7
    const int row0 = blockIdx.x * 128;

    u64 acc[8][4];                  // [row][col-pair], packed f32x2
    #pragma unroll
    for (int i = 0; i < 8; i++)
        #pragma unroll
        for (int j = 0; j < 4; j++) acc[i][j] = 0ull;

    for (int k0 = 0; k0 < INC; k0 += 16) {
        #pragma unroll
        for (int it = 0; it < 2; it++) {
            int f  = tid + it * 256;
            int r  = f & 127;
            int q4 = (f >> 7) * 4;
            int grow = row0 + r;
            float4 a4 = make_float4(0.f, 0.f, 0.f, 0.f);
            if (grow < n)
                a4 = *(const float4*)(x + (size_t)grow * INC + k0 + q4);
            As[q4 + 0][r] = a4.x;
            As[q4 + 1][r] = a4.y;
            As[q4 + 2][r] = a4.z;
            As[q4 + 3][r] = a4.w;
        }
        #pragma unroll
        for (int it = 0; it < 2; it++) {
            int f  = tid + it * 256;
            int kk = f >> 5;
            int c4 = (f & 31) * 4;
            *(float4*)&Bs[kk][c4] =
                *(const float4*)(W + (size_t)(k0 + kk) * HC + c4);
        }
        __syncthreads();

        #pragma unroll
        for (int kk = 0; kk < 16; kk++) {
            float4 a0 = *(const float4*)&As[kk][ty * 8];
            float4 a1 = *(const float4*)&As[kk][ty * 8 + 4];
            float4 b0 = *(const float4*)&Bs[kk][tx * 8];
            float4 b1 = *(const float4*)&Bs[kk][tx * 8 + 4];
            u64 bp[4];
            bp[0] = pack2(b0.x, b0.y); bp[1] = pack2(b0.z, b0.w);
            bp[2] = pack2(b1.x, b1.y); bp[3] = pack2(b1.z, b1.w);
            float a[8] = {a0.x, a0.y, a0.z, a0.w, a1.x, a1.y, a1.z, a1.w};
            #pragma unroll
            for (int i = 0; i < 8; i++) {
                u64 ad = pack_dup(a[i]);
                #pragma unroll
                for (int j = 0; j < 4; j++)
                    acc[i][j] = ffma2(ad, bp[j], acc[i][j]);
            }
        }
        __syncthreads();
    }

    float4 bv0 = *(const float4*)(bias + tx * 8);
    float4 bv1 = *(const float4*)(bias + tx * 8 + 4);
    #pragma unroll
    for (int i = 0; i < 8; i++) {
        int grow = row0 + ty * 8 + i;
        if (grow < n) {
            float2 p0 = unpack2(acc[i][0]);
            float2 p1 = unpack2(acc[i][1]);
            float2 p2 = unpack2(acc[i][2]);
            float2 p3 = unpack2(acc[i][3]);
            float4 o0, o1;
            o0.x = p0.x + bv0.x; o0.y = p0.y + bv0.y;
            o0.z = p1.x + bv0.z; o0.w = p1.y + bv0.w;
            o1.x = p2.x + bv1.x; o1.y = p2.y + bv1.y;
            o1.z = p3.x + bv1.z; o1.w = p3.y + bv1.w;
            *(float4*)(Y + (size_t)grow * HC + tx * 8)     = o0;
            *(float4*)(Y + (size_t)grow * HC + tx * 8 + 4) = o1;
        }
    }
}

// ---------------- kernel 2: degree histogram ----------------
__global__ void hist_kernel(const int* __restrict__ row, int e) {
    int i = blockIdx.x * blockDim.x + threadIdx.x;
    if (i < e) atomicAdd(&g_deg[row[i]], 1);
}

// ---------------- kernels 3a/3b/3c: two-level parallel exclusive scan ----------------
__global__ __launch_bounds__(1024)
void scanA_kernel(int n) {
    __shared__ int sm[1024];
    const int tid = threadIdx.x;
    const int i = blockIdx.x * 1024 + tid;
    int d = (i < n) ? g_deg[i] : 0;
    sm[tid] = d;
    __syncthreads();
    for (int off = 1; off < 1024; off <<= 1) {
        int v = sm[tid];
        int add = (tid >= off) ? sm[tid - off] : 0;
        __syncthreads();
        sm[tid] = v + add;
        __syncthreads();
    }
    if (i < n) g_off[i] = sm[tid] - d;         // exclusive, block-local
    if (tid == 1023) g_bsum[blockIdx.x] = sm[1023];
}

__global__ __launch_bounds__(256)
void scanB_kernel(int nb) {
    __shared__ int sm[256];
    const int tid = threadIdx.x;
    int v = (tid < nb) ? g_bsum[tid] : 0;
    sm[tid] = v;
    __syncthreads();
    for (int off = 1; off < 256; off <<= 1) {
        int x = sm[tid];
        int add = (tid >= off) ? sm[tid - off] : 0;
        __syncthreads();
        sm[tid] = x + add;
        __syncthreads();
    }
    if (tid < nb) g_bbase[tid] = sm[tid] - v;  // exclusive block bases
}

__global__ __launch_bounds__(256)
void scanC_kernel(int n, int e) {
    int i = blockIdx.x * blockDim.x + threadIdx.x;
    if (i < n) {
        int o = g_off[i] + g_bbase[i >> 10];
        g_off[i] = o;
        g_cur[i] = o;
    }
    if (i == 0) g_off[n] = e;
}

// ---------------- kernel 4: scatter edges into CSR ----------------
__global__ void scatter_kernel(const int* __restrict__ row,
                               const int* __restrict__ col, int e) {
    int i = blockIdx.x * blockDim.x + threadIdx.x;
    if (i < e) {
        int d = row[i];
        int p = atomicAdd(&g_cur[d], 1);
        g_ssrc[p] = col[i];
        g_seid[p] = i;
    }
}

// ---------------- kernel 5: per-node attention aggregation + gated skip ----------------
// One warp per destination node. 8 warps / block.
__global__ __launch_bounds__(256)
void agg_kernel(const float* __restrict__ edge_attr,
                const float* __restrict__ We,
                const float* __restrict__ Wbeta,
                float* __restrict__ out, int n)
{
    __shared__ __align__(16) float4 sWe[EDIM][32];
    __shared__ __align__(16) float swa[HC];
    __shared__ __align__(16) float swb[HC];

    const int tid = threadIdx.x;
    for (int f = tid; f < EDIM * 32; f += blockDim.x) {
        int d = f >> 5, l = f & 31;
        sWe[d][l] = *(const float4*)(We + (size_t)d * HC + l * 4);
    }
    for (int c = tid; c < HC; c += blockDim.x) {
        float w0 = Wbeta[c], w1 = Wbeta[HC + c], w2 = Wbeta[2 * HC + c];
        swa[c] = w0 + w2;
        swb[c] = w1 - w2;
    }
    __syncthreads();

    const int warp = tid >> 5;
    const int lane = tid & 31;
    const int node = blockIdx.x * (blockDim.x >> 5) + warp;
    if (node >= n) return;

    const float scale = 0.17677669529663687f;  // 1/sqrt(32)
    float4 q4 = *(const float4*)(g_q + (size_t)node * HC + lane * 4);
    q4.x *= scale; q4.y *= scale; q4.z *= scale; q4.w *= scale;

    float t0 = 0.f, t1 = 0.f;
    {
        float pd[EDIM];
        #pragma unroll
        for (int d = 0; d < EDIM; d++) {
            float4 w = sWe[d][lane];
            pd[d] = q4.x * w.x + q4.y * w.y + q4.z * w.z + q4.w * w.w;
        }
        #pragma unroll
        for (int d = 0; d < EDIM; d++) {
            float s = pd[d];
            s += __shfl_xor_sync(0xffffffffu, s, 1);
            s += __shfl_xor_sync(0xffffffffu, s, 2);
            s += __shfl_xor_sync(0xffffffffu, s, 4);
            if ((lane & 7) == (d >> 1)) {
                if (d & 1) t1 = s; else t0 = s;
            }
        }
    }

    const int start = g_off[node];
    const int end   = g_off[node + 1];
    const int dsel  = 2 * (lane & 7);

    float4 acc = make_float4(0.f, 0.f, 0.f, 0.f);
    float  den = 0.f;

    for (int base = start; base < end; base += 32) {
        int idx = base + lane;
        int s_l = 0, e_l = 0;
        if (idx < end) { s_l = g_ssrc[idx]; e_l = g_seid[idx]; }
        int cnt = min(32, end - base);
        for (int j = 0; j < cnt; j++) {
            int src = __shfl_sync(0xffffffffu, s_l, j);
            int eid = __shfl_sync(0xffffffffu, e_l, j);

            float4 kv = __ldg((const float4*)(g_k + (size_t)src * HC + lane * 4));
            float4 vv = __ldg((const float4*)(g_v + (size_t)src * HC + lane * 4));
            float2 ea = __ldg((const float2*)(edge_attr + (size_t)eid * EDIM + dsel));

            float p = q4.x * kv.x + q4.y * kv.y + q4.z * kv.z + q4.w * kv.w
                    + ea.x * t0 + ea.y * t1;
            p += __shfl_xor_sync(0xffffffffu, p, 1);
            p += __shfl_xor_sync(0xffffffffu, p, 2);
            p += __shfl_xor_sync(0xffffffffu, p, 4);

            float ex = __expf(p);
            den += ex;
            acc.x += ex * vv.x; acc.y += ex * vv.y;
            acc.z += ex * vv.z; acc.w += ex * vv.w;
        }
    }

    float inv = 1.f / (den + 1e-16f);
    float4 o = make_float4(acc.x * inv, acc.y * inv, acc.z * inv, acc.w * inv);
    float4 sk = *(const float4*)(g_skip + (size_t)node * HC + lane * 4);
    float4 wa = *(const float4*)(swa + lane * 4);
    float4 wb = *(const float4*)(swb + lane * 4);

    float s = o.x * wa.x + o.y * wa.y + o.z * wa.z + o.w * wa.w
            + sk.x * wb.x + sk.y * wb.y + sk.z * wb.z + sk.w * wb.w;
    #pragma unroll
    for (int off = 16; off; off >>= 1)
        s += __shfl_xor_sync(0xffffffffu, s, off);

    float beta = 1.f / (1.f + __expf(-s));
    float4 r;
    r.x = beta * sk.x + (1.f - beta) * o.x;
    r.y = beta * sk.y + (1.f - beta) * o.y;
    r.z = beta * sk.z + (1.f - beta) * o.z;
    r.w = beta * sk.w + (1.f - beta) * o.w;
    *(float4*)(out + (size_t)node * HC + lane * 4) = r;
}

// ---------------- launch ----------------
extern "C" void kernel_launch(void* const* d_in, const int* in_sizes, int n_in,
                              void* d_out, int out_size)
{
    const float* x         = (const float*)d_in[0];
    const float* edge_attr = (const float*)d_in[1];
    const int*   eidx      = (const int*)  d_in[2];
    const float* Wq = (const float*)d_in[3];
    const float* bq = (const float*)d_in[4];
    const float* Wk = (const float*)d_in[5];
    const float* bk = (const float*)d_in[6];
    const float* Wv = (const float*)d_in[7];
    const float* bv = (const float*)d_in[8];
    const float* We = (const float*)d_in[9];
    const float* Ws = (const float*)d_in[10];
    const float* bs = (const float*)d_in[11];
    const float* Wb = (const float*)d_in[12];
    float* out = (float*)d_out;

    const int n = in_sizes[0] / INC;        // 100000
    const int e = in_sizes[2] / 2;          // 1600000
    const int* row = eidx;                  // dst
    const int* col = eidx + e;              // src

    zero_deg_kernel<<<(n + 255) / 256, 256>>>(n);

    dim3 ggrid((n + 127) / 128, 1, 4);
    gemm4_kernel<<<ggrid, 256>>>(x, Wq, bq, Wk, bk, Wv, bv, Ws, bs, n);

    hist_kernel<<<(e + 255) / 256, 256>>>(row, e);

    const int nb = (n + 1023) / 1024;       // 98 blocks
    scanA_kernel<<<nb, 1024>>>(n);
    scanB_kernel<<<1, 256>>>(nb);
    scanC_kernel<<<(n + 255) / 256, 256>>>(n, e);

    scatter_kernel<<<(e + 255) / 256, 256>>>(row, col, e);

    agg_kernel<<<(n + 7) / 8, 256>>>(edge_attr, We, Wb, out, n);
}

// round 5
// speedup vs baseline: 1.4971x; 1.2331x over previous
#include <cuda_runtime.h>
#include <cuda_bf16.h>
#include <math.h>

#define N_NODES 100000
#define N_EDGES 1600000
#define HC      128
#define INC     128
#define EDIM    16

// ---------------- scratch (device globals: no allocation allowed) ----------------
__device__ float g_q[(size_t)N_NODES * HC];
__device__ float g_k[(size_t)N_NODES * HC];
__device__ float g_v[(size_t)N_NODES * HC];
__device__ float g_skip[(size_t)N_NODES * HC];
__device__ __nv_bfloat16 g_xh[(size_t)N_NODES * INC];
__device__ __nv_bfloat16 g_xl[(size_t)N_NODES * INC];
__device__ __nv_bfloat16 g_wh[4 * INC * HC];
__device__ __nv_bfloat16 g_wl[4 * INC * HC];
__device__ int   g_deg[N_NODES];
__device__ int   g_off[N_NODES + 1];
__device__ int   g_cur[N_NODES];
__device__ int   g_ssrc[N_EDGES];
__device__ int   g_seid[N_EDGES];
__device__ int   g_bsum[256];
__device__ int   g_bbase[256];

// ---------------- mma / ldmatrix helpers ----------------
static __device__ __forceinline__ unsigned smem_u32(const void* p) {
    return (unsigned)__cvta_generic_to_shared(p);
}
static __device__ __forceinline__ void ldsm_x4(unsigned* r, unsigned addr) {
    asm volatile("ldmatrix.sync.aligned.m8n8.x4.shared.b16 {%0,%1,%2,%3}, [%4];"
        : "=r"(r[0]), "=r"(r[1]), "=r"(r[2]), "=r"(r[3]) : "r"(addr));
}
static __device__ __forceinline__ void ldsm_x4t(unsigned* r, unsigned addr) {
    asm volatile("ldmatrix.sync.aligned.m8n8.x4.trans.shared.b16 {%0,%1,%2,%3}, [%4];"
        : "=r"(r[0]), "=r"(r[1]), "=r"(r[2]), "=r"(r[3]) : "r"(addr));
}
static __device__ __forceinline__ void mma_bf16(float* d, const unsigned* a, const unsigned* b) {
    asm volatile("mma.sync.aligned.m16n8k16.row.col.f32.bf16.bf16.f32 "
        "{%0,%1,%2,%3}, {%4,%5,%6,%7}, {%8,%9}, {%0,%1,%2,%3};"
        : "+f"(d[0]), "+f"(d[1]), "+f"(d[2]), "+f"(d[3])
        : "r"(a[0]), "r"(a[1]), "r"(a[2]), "r"(a[3]), "r"(b[0]), "r"(b[1]));
}

// ---------------- kernel 0: zero degree histogram ----------------
__global__ void zero_deg_kernel(int n) {
    int i = blockIdx.x * blockDim.x + threadIdx.x;
    if (i < n) g_deg[i] = 0;
}

// ---------------- kernel: degree histogram ----------------
__global__ void hist_kernel(const int* __restrict__ row, int e) {
    int i = blockIdx.x * blockDim.x + threadIdx.x;
    if (i < e) atomicAdd(&g_deg[row[i]], 1);
}

// ---------------- kernel: split fp32 -> (hi, lo) bf16 for x and the 4 W's ----------------
__global__ void convert_kernel(const float* __restrict__ x,
                               const float* __restrict__ Wq,
                               const float* __restrict__ Wk,
                               const float* __restrict__ Wv,
                               const float* __restrict__ Ws,
                               int n)
{
    const int totalx4 = n * (INC / 4);
    int i = blockIdx.x * blockDim.x + threadIdx.x;
    const float* src; __nv_bfloat16 *dh, *dl; int off4;
    if (i < totalx4) {
        src = x; dh = g_xh; dl = g_xl; off4 = i;
    } else {
        int wi = i - totalx4;
        if (wi >= 4 * (INC * HC / 4)) return;
        int which = wi >> 12;               // 4096 float4 per W
        int o     = wi & 4095;
        src = (which == 0) ? Wq : (which == 1) ? Wk : (which == 2) ? Wv : Ws;
        dh = g_wh + which * (INC * HC);
        dl = g_wl + which * (INC * HC);
        off4 = o;
    }
    float4 v = ((const float4*)src)[off4];
    __nv_bfloat16 h0 = __float2bfloat16_rn(v.x);
    __nv_bfloat16 h1 = __float2bfloat16_rn(v.y);
    __nv_bfloat16 h2 = __float2bfloat16_rn(v.z);
    __nv_bfloat16 h3 = __float2bfloat16_rn(v.w);
    __nv_bfloat16 l0 = __float2bfloat16_rn(v.x - __bfloat162float(h0));
    __nv_bfloat16 l1 = __float2bfloat16_rn(v.y - __bfloat162float(h1));
    __nv_bfloat16 l2 = __float2bfloat16_rn(v.z - __bfloat162float(h2));
    __nv_bfloat16 l3 = __float2bfloat16_rn(v.w - __bfloat162float(h3));
    __nv_bfloat162 ph01, ph23, pl01, pl23;
    ph01.x = h0; ph01.y = h1; ph23.x = h2; ph23.y = h3;
    pl01.x = l0; pl01.y = l1; pl23.x = l2; pl23.y = l3;
    ((__nv_bfloat162*)dh)[off4 * 2]     = ph01;
    ((__nv_bfloat162*)dh)[off4 * 2 + 1] = ph23;
    ((__nv_bfloat162*)dl)[off4 * 2]     = pl01;
    ((__nv_bfloat162*)dl)[off4 * 2 + 1] = pl23;
}

// ---------------- kernel: tensor-core GEMM  Y = X @ W + b (bf16 split x3 MMA) ----------------
// 512 threads, 16 warps in a 4x4 grid of 32x32 warp tiles over a 128x128 block tile.
__global__ __launch_bounds__(512)
void gemm_mma_kernel(const float* __restrict__ bq, const float* __restrict__ bk,
                     const float* __restrict__ bv, const float* __restrict__ bs,
                     int n)
{
    const __nv_bfloat16* Wh = g_wh + blockIdx.z * (INC * HC);
    const __nv_bfloat16* Wl = g_wl + blockIdx.z * (INC * HC);
    const float* bias; float* Y;
    switch (blockIdx.z) {
        case 0:  bias = bq; Y = g_q;    break;
        case 1:  bias = bk; Y = g_k;    break;
        case 2:  bias = bv; Y = g_v;    break;
        default: bias = bs; Y = g_skip; break;
    }

    // A tile: 128 rows x 32 k, row stride 40 bf16 (80 B, conflict-free ldmatrix)
    // B tile: 32 k x 128 n, row stride 136 bf16 (272 B, conflict-free trans ldmatrix)
    __shared__ __nv_bfloat16 sAh[128 * 40], sAl[128 * 40];
    __shared__ __nv_bfloat16 sBh[32 * 136], sBl[32 * 136];

    const int tid = threadIdx.x;
    const int w   = tid >> 5, l = tid & 31;
    const int wm  = w & 3,  wn = w >> 2;      // warp tile: rows wm*32, cols wn*32
    const int row0 = blockIdx.x * 128;
    const int g = l >> 3, r = l & 7;          // ldmatrix address group / row-in-matrix

    float acc[2][4][4];
    #pragma unroll
    for (int mi = 0; mi < 2; mi++)
        #pragma unroll
        for (int ni = 0; ni < 4; ni++)
            #pragma unroll
            for (int jj = 0; jj < 4; jj++) acc[mi][ni][jj] = 0.f;

    for (int k0 = 0; k0 < INC; k0 += 32) {
        // load A (hi, lo): 128x32 bf16 each, 8-byte chunks
        #pragma unroll
        for (int it = 0; it < 2; it++) {
            int c = tid + it * 512;           // 0..1023
            int row = c >> 3;
            int kk  = (c & 7) * 4;
            int grow = row0 + row;
            unsigned long long vh = 0ull, vl = 0ull;
            if (grow < n) {
                vh = *(const unsigned long long*)(g_xh + (size_t)grow * INC + k0 + kk);
                vl = *(const unsigned long long*)(g_xl + (size_t)grow * INC + k0 + kk);
            }
            *(unsigned long long*)(sAh + row * 40 + kk) = vh;
            *(unsigned long long*)(sAl + row * 40 + kk) = vl;
        }
        // load B (hi, lo): 32x128 bf16 each
        #pragma unroll
        for (int it = 0; it < 2; it++) {
            int c = tid + it * 512;
            int kk = c >> 5;
            int nn = (c & 31) * 4;
            *(unsigned long long*)(sBh + kk * 136 + nn) =
                *(const unsigned long long*)(Wh + (size_t)(k0 + kk) * HC + nn);
            *(unsigned long long*)(sBl + kk * 136 + nn) =
                *(const unsigned long long*)(Wl + (size_t)(k0 + kk) * HC + nn);
        }
        __syncthreads();

        #pragma unroll
        for (int k16 = 0; k16 < 32; k16 += 16) {
            // A fragments (2 m-tiles x 16k), hi and lo
            unsigned ah[2][4], al[2][4];
            #pragma unroll
            for (int mi = 0; mi < 2; mi++) {
                int arow = wm * 32 + mi * 16 + (g & 1) * 8 + r;
                int koff = k16 + (g >> 1) * 8;
                ldsm_x4(ah[mi], smem_u32(sAh + arow * 40 + koff));
                ldsm_x4(al[mi], smem_u32(sAl + arow * 40 + koff));
            }
            // B fragments: 2 pairs of n-tiles (16 n each).
            // FIX: per-lane row term (krow + r) — each of the 8 lanes in an
            // address group must point at a distinct k-row of the 8x8 block.
            #pragma unroll
            for (int nip = 0; nip < 2; nip++) {
                int krow = k16 + (g & 1) * 8 + r;
                int nc   = wn * 32 + nip * 16 + (g >> 1) * 8;
                unsigned bh[4], bl[4];
                ldsm_x4t(bh, smem_u32(sBh + krow * 136 + nc));
                ldsm_x4t(bl, smem_u32(sBl + krow * 136 + nc));
                #pragma unroll
                for (int nj = 0; nj < 2; nj++) {
                    int ni = nip * 2 + nj;
                    #pragma unroll
                    for (int mi = 0; mi < 2; mi++) {
                        mma_bf16(acc[mi][ni], ah[mi], bh + nj * 2);
                        mma_bf16(acc[mi][ni], ah[mi], bl + nj * 2);
                        mma_bf16(acc[mi][ni], al[mi], bh + nj * 2);
                    }
                }
            }
        }
        __syncthreads();
    }

    // epilogue: bias + store (d0,d1 -> row, d2,d3 -> row+8)
    #pragma unroll
    for (int mi = 0; mi < 2; mi++) {
        #pragma unroll
        for (int ni = 0; ni < 4; ni++) {
            int col = wn * 32 + ni * 8 + (l & 3) * 2;
            int row = row0 + wm * 32 + mi * 16 + (l >> 2);
            float b0 = bias[col], b1 = bias[col + 1];
            if (row < n) {
                float2 v0 = make_float2(acc[mi][ni][0] + b0, acc[mi][ni][1] + b1);
                *(float2*)(Y + (size_t)row * HC + col) = v0;
            }
            if (row + 8 < n) {
                float2 v1 = make_float2(acc[mi][ni][2] + b0, acc[mi][ni][3] + b1);
                *(float2*)(Y + (size_t)(row + 8) * HC + col) = v1;
            }
        }
    }
}

// ---------------- kernels: two-level parallel exclusive scan ----------------
__global__ __launch_bounds__(1024)
void scanA_kernel(int n) {
    __shared__ int sm[1024];
    const int tid = threadIdx.x;
    const int i = blockIdx.x * 1024 + tid;
    int d = (i < n) ? g_deg[i] : 0;
    sm[tid] = d;
    __syncthreads();
    for (int off = 1; off < 1024; off <<= 1) {
        int v = sm[tid];
        int add = (tid >= off) ? sm[tid - off] : 0;
        __syncthreads();
        sm[tid] = v + add;
        __syncthreads();
    }
    if (i < n) g_off[i] = sm[tid] - d;
    if (tid == 1023) g_bsum[blockIdx.x] = sm[1023];
}

__global__ __launch_bounds__(256)
void scanB_kernel(int nb) {
    __shared__ int sm[256];
    const int tid = threadIdx.x;
    int v = (tid < nb) ? g_bsum[tid] : 0;
    sm[tid] = v;
    __syncthreads();
    for (int off = 1; off < 256; off <<= 1) {
        int x = sm[tid];
        int add = (tid >= off) ? sm[tid - off] : 0;
        __syncthreads();
        sm[tid] = x + add;
        __syncthreads();
    }
    if (tid < nb) g_bbase[tid] = sm[tid] - v;
}

__global__ __launch_bounds__(256)
void scanC_kernel(int n, int e) {
    int i = blockIdx.x * blockDim.x + threadIdx.x;
    if (i < n) {
        int o = g_off[i] + g_bbase[i >> 10];
        g_off[i] = o;
        g_cur[i] = o;
    }
    if (i == 0) g_off[n] = e;
}

// ---------------- kernel: scatter edges into CSR ----------------
__global__ void scatter_kernel(const int* __restrict__ row,
                               const int* __restrict__ col, int e) {
    int i = blockIdx.x * blockDim.x + threadIdx.x;
    if (i < e) {
        int d = row[i];
        int p = atomicAdd(&g_cur[d], 1);
        g_ssrc[p] = col[i];
        g_seid[p] = i;
    }
}

// ---------------- kernel: per-node attention aggregation + gated skip ----------------
__global__ __launch_bounds__(256)
void agg_kernel(const float* __restrict__ edge_attr,
                const float* __restrict__ We,
                const float* __restrict__ Wbeta,
                float* __restrict__ out, int n)
{
    __shared__ __align__(16) float4 sWe[EDIM][32];
    __shared__ __align__(16) float swa[HC];
    __shared__ __align__(16) float swb[HC];

    const int tid = threadIdx.x;
    for (int f = tid; f < EDIM * 32; f += blockDim.x) {
        int d = f >> 5, l = f & 31;
        sWe[d][l] = *(const float4*)(We + (size_t)d * HC + l * 4);
    }
    for (int c = tid; c < HC; c += blockDim.x) {
        float w0 = Wbeta[c], w1 = Wbeta[HC + c], w2 = Wbeta[2 * HC + c];
        swa[c] = w0 + w2;
        swb[c] = w1 - w2;
    }
    __syncthreads();

    const int warp = tid >> 5;
    const int lane = tid & 31;
    const int node = blockIdx.x * (blockDim.x >> 5) + warp;
    if (node >= n) return;

    const float scale = 0.17677669529663687f;  // 1/sqrt(32)
    float4 q4 = *(const float4*)(g_q + (size_t)node * HC + lane * 4);
    q4.x *= scale; q4.y *= scale; q4.z *= scale; q4.w *= scale;

    float t0 = 0.f, t1 = 0.f;
    {
        float pd[EDIM];
        #pragma unroll
        for (int d = 0; d < EDIM; d++) {
            float4 w = sWe[d][lane];
            pd[d] = q4.x * w.x + q4.y * w.y + q4.z * w.z + q4.w * w.w;
        }
        #pragma unroll
        for (int d = 0; d < EDIM; d++) {
            float s = pd[d];
            s += __shfl_xor_sync(0xffffffffu, s, 1);
            s += __shfl_xor_sync(0xffffffffu, s, 2);
            s += __shfl_xor_sync(0xffffffffu, s, 4);
            if ((lane & 7) == (d >> 1)) {
                if (d & 1) t1 = s; else t0 = s;
            }
        }
    }

    const int start = g_off[node];
    const int end   = g_off[node + 1];
    const int dsel  = 2 * (lane & 7);

    float4 acc = make_float4(0.f, 0.f, 0.f, 0.f);
    float  den = 0.f;

    for (int base = start; base < end; base += 32) {
        int idx = base + lane;
        int s_l = 0, e_l = 0;
        if (idx < end) { s_l = g_ssrc[idx]; e_l = g_seid[idx]; }
        int cnt = min(32, end - base);
        for (int j = 0; j < cnt; j++) {
            int src = __shfl_sync(0xffffffffu, s_l, j);
            int eid = __shfl_sync(0xffffffffu, e_l, j);

            float4 kv = __ldg((const float4*)(g_k + (size_t)src * HC + lane * 4));
            float4 vv = __ldg((const float4*)(g_v + (size_t)src * HC + lane * 4));
            float2 ea = __ldg((const float2*)(edge_attr + (size_t)eid * EDIM + dsel));

            float p = q4.x * kv.x + q4.y * kv.y + q4.z * kv.z + q4.w * kv.w
                    + ea.x * t0 + ea.y * t1;
            p += __shfl_xor_sync(0xffffffffu, p, 1);
            p += __shfl_xor_sync(0xffffffffu, p, 2);
            p += __shfl_xor_sync(0xffffffffu, p, 4);

            float ex = __expf(p);
            den += ex;
            acc.x += ex * vv.x; acc.y += ex * vv.y;
            acc.z += ex * vv.z; acc.w += ex * vv.w;
        }
    }

    float inv = 1.f / (den + 1e-16f);
    float4 o = make_float4(acc.x * inv, acc.y * inv, acc.z * inv, acc.w * inv);
    float4 sk = *(const float4*)(g_skip + (size_t)node * HC + lane * 4);
    float4 wa = *(const float4*)(swa + lane * 4);
    float4 wb = *(const float4*)(swb + lane * 4);

    float s = o.x * wa.x + o.y * wa.y + o.z * wa.z + o.w * wa.w
            + sk.x * wb.x + sk.y * wb.y + sk.z * wb.z + sk.w * wb.w;
    #pragma unroll
    for (int off = 16; off; off >>= 1)
        s += __shfl_xor_sync(0xffffffffu, s, off);

    float beta = 1.f / (1.f + __expf(-s));
    float4 r;
    r.x = beta * sk.x + (1.f - beta) * o.x;
    r.y = beta * sk.y + (1.f - beta) * o.y;
    r.z = beta * sk.z + (1.f - beta) * o.z;
    r.w = beta * sk.w + (1.f - beta) * o.w;
    *(float4*)(out + (size_t)node * HC + lane * 4) = r;
}

// ---------------- launch ----------------
extern "C" void kernel_launch(void* const* d_in, const int* in_sizes, int n_in,
                              void* d_out, int out_size)
{
    const float* x         = (const float*)d_in[0];
    const float* edge_attr = (const float*)d_in[1];
    const int*   eidx      = (const int*)  d_in[2];
    const float* Wq = (const float*)d_in[3];
    const float* bq = (const float*)d_in[4];
    const float* Wk = (const float*)d_in[5];
    const float* bk = (const float*)d_in[6];
    const float* Wv = (const float*)d_in[7];
    const float* bv = (const float*)d_in[8];
    const float* We = (const float*)d_in[9];
    const float* Ws = (const float*)d_in[10];
    const float* bs = (const float*)d_in[11];
    const float* Wb = (const float*)d_in[12];
    float* out = (float*)d_out;

    const int n = in_sizes[0] / INC;        // 100000
    const int e = in_sizes[2] / 2;          // 1600000
    const int* row = eidx;                  // dst
    const int* col = eidx + e;              // src

    zero_deg_kernel<<<(n + 255) / 256, 256>>>(n);
    hist_kernel<<<(e + 255) / 256, 256>>>(row, e);

    const int cvt_items = n * (INC / 4) + 4 * (INC * HC / 4);
    convert_kernel<<<(cvt_items + 255) / 256, 256>>>(x, Wq, Wk, Wv, Ws, n);

    dim3 ggrid((n + 127) / 128, 1, 4);
    gemm_mma_kernel<<<ggrid, 512>>>(bq, bk, bv, bs, n);

    const int nb = (n + 1023) / 1024;
    scanA_kernel<<<nb, 1024>>>(n);
    scanB_kernel<<<1, 256>>>(nb);
    scanC_kernel<<<(n + 255) / 256, 256>>>(n, e);

    scatter_kernel<<<(e + 255) / 256, 256>>>(row, col, e);

    agg_kernel<<<(n + 7) / 8, 256>>>(edge_attr, We, Wb, out, n);
}

// round 6
// speedup vs baseline: 1.6997x; 1.1353x over previous
#include <cuda_runtime.h>
#include <cuda_bf16.h>
#include <math.h>

#define N_NODES 100000
#define N_EDGES 1600000
#define HC      128
#define INC     128
#define EDIM    16

// ---------------- scratch (device globals: no allocation allowed) ----------------
__device__ float g_q[(size_t)N_NODES * HC];
__device__ float g_skip[(size_t)N_NODES * HC];
__device__ __nv_bfloat16 g_kh[(size_t)N_NODES * HC];
__device__ __nv_bfloat16 g_vh[(size_t)N_NODES * HC];
__device__ __nv_bfloat16 g_xh[(size_t)N_NODES * INC];
__device__ __nv_bfloat16 g_xl[(size_t)N_NODES * INC];
__device__ __nv_bfloat16 g_wh[4 * INC * HC];
__device__ __nv_bfloat16 g_wl[4 * INC * HC];
__device__ int   g_deg[N_NODES];
__device__ int   g_off[N_NODES + 1];
__device__ int   g_cur[N_NODES];
__device__ int   g_ssrc[N_EDGES];
__device__ int   g_seid[N_EDGES];
__device__ int   g_bsum[256];
__device__ int   g_bbase[256];

// ---------------- helpers ----------------
static __device__ __forceinline__ unsigned smem_u32(const void* p) {
    return (unsigned)__cvta_generic_to_shared(p);
}
static __device__ __forceinline__ void ldsm_x4(unsigned* r, unsigned addr) {
    asm volatile("ldmatrix.sync.aligned.m8n8.x4.shared.b16 {%0,%1,%2,%3}, [%4];"
        : "=r"(r[0]), "=r"(r[1]), "=r"(r[2]), "=r"(r[3]) : "r"(addr));
}
static __device__ __forceinline__ void ldsm_x4t(unsigned* r, unsigned addr) {
    asm volatile("ldmatrix.sync.aligned.m8n8.x4.trans.shared.b16 {%0,%1,%2,%3}, [%4];"
        : "=r"(r[0]), "=r"(r[1]), "=r"(r[2]), "=r"(r[3]) : "r"(addr));
}
static __device__ __forceinline__ void mma_bf16(float* d, const unsigned* a, const unsigned* b) {
    asm volatile("mma.sync.aligned.m16n8k16.row.col.f32.bf16.bf16.f32 "
        "{%0,%1,%2,%3}, {%4,%5,%6,%7}, {%8,%9}, {%0,%1,%2,%3};"
        : "+f"(d[0]), "+f"(d[1]), "+f"(d[2]), "+f"(d[3])
        : "r"(a[0]), "r"(a[1]), "r"(a[2]), "r"(a[3]), "r"(b[0]), "r"(b[1]));
}
// bf16(bits in low/high half of u32) -> f32 by shift
static __device__ __forceinline__ float bf_lo(unsigned u) { return __uint_as_float(u << 16); }
static __device__ __forceinline__ float bf_hi(unsigned u) { return __uint_as_float(u & 0xffff0000u); }

// ---------------- kernel 0: zero degree histogram ----------------
__global__ void zero_deg_kernel(int n) {
    int i = blockIdx.x * blockDim.x + threadIdx.x;
    if (i < n) g_deg[i] = 0;
}

// ---------------- kernel: degree histogram ----------------
__global__ void hist_kernel(const int* __restrict__ row, int e) {
    int i = blockIdx.x * blockDim.x + threadIdx.x;
    if (i < e) atomicAdd(&g_deg[row[i]], 1);
}

// ---------------- kernel: split fp32 -> (hi, lo) bf16 for x and the 4 W's ----------------
__global__ void convert_kernel(const float* __restrict__ x,
                               const float* __restrict__ Wq,
                               const float* __restrict__ Wk,
                               const float* __restrict__ Wv,
                               const float* __restrict__ Ws,
                               int n)
{
    const int totalx4 = n * (INC / 4);
    int i = blockIdx.x * blockDim.x + threadIdx.x;
    const float* src; __nv_bfloat16 *dh, *dl; int off4;
    if (i < totalx4) {
        src = x; dh = g_xh; dl = g_xl; off4 = i;
    } else {
        int wi = i - totalx4;
        if (wi >= 4 * (INC * HC / 4)) return;
        int which = wi >> 12;               // 4096 float4 per W
        int o     = wi & 4095;
        src = (which == 0) ? Wq : (which == 1) ? Wk : (which == 2) ? Wv : Ws;
        dh = g_wh + which * (INC * HC);
        dl = g_wl + which * (INC * HC);
        off4 = o;
    }
    float4 v = ((const float4*)src)[off4];
    __nv_bfloat16 h0 = __float2bfloat16_rn(v.x);
    __nv_bfloat16 h1 = __float2bfloat16_rn(v.y);
    __nv_bfloat16 h2 = __float2bfloat16_rn(v.z);
    __nv_bfloat16 h3 = __float2bfloat16_rn(v.w);
    __nv_bfloat16 l0 = __float2bfloat16_rn(v.x - __bfloat162float(h0));
    __nv_bfloat16 l1 = __float2bfloat16_rn(v.y - __bfloat162float(h1));
    __nv_bfloat16 l2 = __float2bfloat16_rn(v.z - __bfloat162float(h2));
    __nv_bfloat16 l3 = __float2bfloat16_rn(v.w - __bfloat162float(h3));
    __nv_bfloat162 ph01, ph23, pl01, pl23;
    ph01.x = h0; ph01.y = h1; ph23.x = h2; ph23.y = h3;
    pl01.x = l0; pl01.y = l1; pl23.x = l2; pl23.y = l3;
    ((__nv_bfloat162*)dh)[off4 * 2]     = ph01;
    ((__nv_bfloat162*)dh)[off4 * 2 + 1] = ph23;
    ((__nv_bfloat162*)dl)[off4 * 2]     = pl01;
    ((__nv_bfloat162*)dl)[off4 * 2 + 1] = pl23;
}

// ---------------- kernel: tensor-core GEMM  Y = X @ W + b (bf16 split x3 MMA) ----------------
// 512 threads, 16 warps in a 4x4 grid of 32x32 warp tiles over a 128x128 block tile.
// launch_bounds(512,2): cap regs at 64 so 2 CTAs/SM fit (occupancy 24% -> ~50%).
// q, skip stored fp32; k, v stored bf16 (halves agg gather traffic).
__global__ __launch_bounds__(512, 2)
void gemm_mma_kernel(const float* __restrict__ bq, const float* __restrict__ bk,
                     const float* __restrict__ bv, const float* __restrict__ bs,
                     int n)
{
    const __nv_bfloat16* Wh = g_wh + blockIdx.z * (INC * HC);
    const __nv_bfloat16* Wl = g_wl + blockIdx.z * (INC * HC);
    const float* bias; float* Yf = 0; __nv_bfloat16* Yh = 0;
    switch (blockIdx.z) {
        case 0:  bias = bq; Yf = g_q;    break;
        case 1:  bias = bk; Yh = g_kh;   break;
        case 2:  bias = bv; Yh = g_vh;   break;
        default: bias = bs; Yf = g_skip; break;
    }

    __shared__ __nv_bfloat16 sAh[128 * 40], sAl[128 * 40];
    __shared__ __nv_bfloat16 sBh[32 * 136], sBl[32 * 136];

    const int tid = threadIdx.x;
    const int w   = tid >> 5, l = tid & 31;
    const int wm  = w & 3,  wn = w >> 2;
    const int row0 = blockIdx.x * 128;
    const int g = l >> 3, r = l & 7;

    float acc[2][4][4];
    #pragma unroll
    for (int mi = 0; mi < 2; mi++)
        #pragma unroll
        for (int ni = 0; ni < 4; ni++)
            #pragma unroll
            for (int jj = 0; jj < 4; jj++) acc[mi][ni][jj] = 0.f;

    for (int k0 = 0; k0 < INC; k0 += 32) {
        #pragma unroll
        for (int it = 0; it < 2; it++) {
            int c = tid + it * 512;
            int row = c >> 3;
            int kk  = (c & 7) * 4;
            int grow = row0 + row;
            unsigned long long vh = 0ull, vl = 0ull;
            if (grow < n) {
                vh = *(const unsigned long long*)(g_xh + (size_t)grow * INC + k0 + kk);
                vl = *(const unsigned long long*)(g_xl + (size_t)grow * INC + k0 + kk);
            }
            *(unsigned long long*)(sAh + row * 40 + kk) = vh;
            *(unsigned long long*)(sAl + row * 40 + kk) = vl;
        }
        #pragma unroll
        for (int it = 0; it < 2; it++) {
            int c = tid + it * 512;
            int kk = c >> 5;
            int nn = (c & 31) * 4;
            *(unsigned long long*)(sBh + kk * 136 + nn) =
                *(const unsigned long long*)(Wh + (size_t)(k0 + kk) * HC + nn);
            *(unsigned long long*)(sBl + kk * 136 + nn) =
                *(const unsigned long long*)(Wl + (size_t)(k0 + kk) * HC + nn);
        }
        __syncthreads();

        #pragma unroll
        for (int k16 = 0; k16 < 32; k16 += 16) {
            unsigned ah[2][4], al[2][4];
            #pragma unroll
            for (int mi = 0; mi < 2; mi++) {
                int arow = wm * 32 + mi * 16 + (g & 1) * 8 + r;
                int koff = k16 + (g >> 1) * 8;
                ldsm_x4(ah[mi], smem_u32(sAh + arow * 40 + koff));
                ldsm_x4(al[mi], smem_u32(sAl + arow * 40 + koff));
            }
            #pragma unroll
            for (int nip = 0; nip < 2; nip++) {
                int krow = k16 + (g & 1) * 8 + r;
                int nc   = wn * 32 + nip * 16 + (g >> 1) * 8;
                unsigned bh[4], bl[4];
                ldsm_x4t(bh, smem_u32(sBh + krow * 136 + nc));
                ldsm_x4t(bl, smem_u32(sBl + krow * 136 + nc));
                #pragma unroll
                for (int nj = 0; nj < 2; nj++) {
                    int ni = nip * 2 + nj;
                    #pragma unroll
                    for (int mi = 0; mi < 2; mi++) {
                        mma_bf16(acc[mi][ni], ah[mi], bh + nj * 2);
                        mma_bf16(acc[mi][ni], ah[mi], bl + nj * 2);
                        mma_bf16(acc[mi][ni], al[mi], bh + nj * 2);
                    }
                }
            }
        }
        __syncthreads();
    }

    // epilogue: bias + store (d0,d1 -> row, d2,d3 -> row+8)
    #pragma unroll
    for (int mi = 0; mi < 2; mi++) {
        #pragma unroll
        for (int ni = 0; ni < 4; ni++) {
            int col = wn * 32 + ni * 8 + (l & 3) * 2;
            int row = row0 + wm * 32 + mi * 16 + (l >> 2);
            float b0 = bias[col], b1 = bias[col + 1];
            float f0 = acc[mi][ni][0] + b0, f1 = acc[mi][ni][1] + b1;
            float f2 = acc[mi][ni][2] + b0, f3 = acc[mi][ni][3] + b1;
            if (Yh) {
                if (row < n)
                    *(__nv_bfloat162*)(Yh + (size_t)row * HC + col) =
                        __float22bfloat162_rn(make_float2(f0, f1));
                if (row + 8 < n)
                    *(__nv_bfloat162*)(Yh + (size_t)(row + 8) * HC + col) =
                        __float22bfloat162_rn(make_float2(f2, f3));
            } else {
                if (row < n)
                    *(float2*)(Yf + (size_t)row * HC + col) = make_float2(f0, f1);
                if (row + 8 < n)
                    *(float2*)(Yf + (size_t)(row + 8) * HC + col) = make_float2(f2, f3);
            }
        }
    }
}

// ---------------- kernels: two-level parallel exclusive scan ----------------
__global__ __launch_bounds__(1024)
void scanA_kernel(int n) {
    __shared__ int sm[1024];
    const int tid = threadIdx.x;
    const int i = blockIdx.x * 1024 + tid;
    int d = (i < n) ? g_deg[i] : 0;
    sm[tid] = d;
    __syncthreads();
    for (int off = 1; off < 1024; off <<= 1) {
        int v = sm[tid];
        int add = (tid >= off) ? sm[tid - off] : 0;
        __syncthreads();
        sm[tid] = v + add;
        __syncthreads();
    }
    if (i < n) g_off[i] = sm[tid] - d;
    if (tid == 1023) g_bsum[blockIdx.x] = sm[1023];
}

__global__ __launch_bounds__(256)
void scanB_kernel(int nb) {
    __shared__ int sm[256];
    const int tid = threadIdx.x;
    int v = (tid < nb) ? g_bsum[tid] : 0;
    sm[tid] = v;
    __syncthreads();
    for (int off = 1; off < 256; off <<= 1) {
        int x = sm[tid];
        int add = (tid >= off) ? sm[tid - off] : 0;
        __syncthreads();
        sm[tid] = x + add;
        __syncthreads();
    }
    if (tid < nb) g_bbase[tid] = sm[tid] - v;
}

__global__ __launch_bounds__(256)
void scanC_kernel(int n, int e) {
    int i = blockIdx.x * blockDim.x + threadIdx.x;
    if (i < n) {
        int o = g_off[i] + g_bbase[i >> 10];
        g_off[i] = o;
        g_cur[i] = o;
    }
    if (i == 0) g_off[n] = e;
}

// ---------------- kernel: scatter edges into CSR ----------------
__global__ void scatter_kernel(const int* __restrict__ row,
                               const int* __restrict__ col, int e) {
    int i = blockIdx.x * blockDim.x + threadIdx.x;
    if (i < e) {
        int d = row[i];
        int p = atomicAdd(&g_cur[d], 1);
        g_ssrc[p] = col[i];
        g_seid[p] = i;
    }
}

// ---------------- kernel: per-node attention aggregation + gated skip ----------------
__global__ __launch_bounds__(256)
void agg_kernel(const float* __restrict__ edge_attr,
                const float* __restrict__ We,
                const float* __restrict__ Wbeta,
                float* __restrict__ out, int n)
{
    __shared__ __align__(16) float4 sWe[EDIM][32];
    __shared__ __align__(16) float swa[HC];
    __shared__ __align__(16) float swb[HC];

    const int tid = threadIdx.x;
    for (int f = tid; f < EDIM * 32; f += blockDim.x) {
        int d = f >> 5, l = f & 31;
        sWe[d][l] = *(const float4*)(We + (size_t)d * HC + l * 4);
    }
    for (int c = tid; c < HC; c += blockDim.x) {
        float w0 = Wbeta[c], w1 = Wbeta[HC + c], w2 = Wbeta[2 * HC + c];
        swa[c] = w0 + w2;
        swb[c] = w1 - w2;
    }
    __syncthreads();

    const int warp = tid >> 5;
    const int lane = tid & 31;
    const int node = blockIdx.x * (blockDim.x >> 5) + warp;
    if (node >= n) return;

    const float scale = 0.17677669529663687f;  // 1/sqrt(32)
    float4 q4 = *(const float4*)(g_q + (size_t)node * HC + lane * 4);
    q4.x *= scale; q4.y *= scale; q4.z *= scale; q4.w *= scale;

    float t0 = 0.f, t1 = 0.f;
    {
        float pd[EDIM];
        #pragma unroll
        for (int d = 0; d < EDIM; d++) {
            float4 w = sWe[d][lane];
            pd[d] = q4.x * w.x + q4.y * w.y + q4.z * w.z + q4.w * w.w;
        }
        #pragma unroll
        for (int d = 0; d < EDIM; d++) {
            float s = pd[d];
            s += __shfl_xor_sync(0xffffffffu, s, 1);
            s += __shfl_xor_sync(0xffffffffu, s, 2);
            s += __shfl_xor_sync(0xffffffffu, s, 4);
            if ((lane & 7) == (d >> 1)) {
                if (d & 1) t1 = s; else t0 = s;
            }
        }
    }

    const int start = g_off[node];
    const int end   = g_off[node + 1];
    const int dsel  = 2 * (lane & 7);

    float4 acc = make_float4(0.f, 0.f, 0.f, 0.f);
    float  den = 0.f;

    for (int base = start; base < end; base += 32) {
        int idx = base + lane;
        int s_l = 0, e_l = 0;
        if (idx < end) { s_l = g_ssrc[idx]; e_l = g_seid[idx]; }
        int cnt = min(32, end - base);
        for (int j = 0; j < cnt; j++) {
            int src = __shfl_sync(0xffffffffu, s_l, j);
            int eid = __shfl_sync(0xffffffffu, e_l, j);

            uint2 uk = __ldg((const uint2*)(g_kh + (size_t)src * HC + lane * 4));
            uint2 uv = __ldg((const uint2*)(g_vh + (size_t)src * HC + lane * 4));
            float2 ea = __ldg((const float2*)(edge_attr + (size_t)eid * EDIM + dsel));

            float p = q4.x * bf_lo(uk.x) + q4.y * bf_hi(uk.x)
                    + q4.z * bf_lo(uk.y) + q4.w * bf_hi(uk.y)
                    + ea.x * t0 + ea.y * t1;
            p += __shfl_xor_sync(0xffffffffu, p, 1);
            p += __shfl_xor_sync(0xffffffffu, p, 2);
            p += __shfl_xor_sync(0xffffffffu, p, 4);

            float ex = __expf(p);
            den += ex;
            acc.x += ex * bf_lo(uv.x); acc.y += ex * bf_hi(uv.x);
            acc.z += ex * bf_lo(uv.y); acc.w += ex * bf_hi(uv.y);
        }
    }

    float inv = 1.f / (den + 1e-16f);
    float4 o = make_float4(acc.x * inv, acc.y * inv, acc.z * inv, acc.w * inv);
    float4 sk = *(const float4*)(g_skip + (size_t)node * HC + lane * 4);
    float4 wa = *(const float4*)(swa + lane * 4);
    float4 wb = *(const float4*)(swb + lane * 4);

    float s = o.x * wa.x + o.y * wa.y + o.z * wa.z + o.w * wa.w
            + sk.x * wb.x + sk.y * wb.y + sk.z * wb.z + sk.w * wb.w;
    #pragma unroll
    for (int off = 16; off; off >>= 1)
        s += __shfl_xor_sync(0xffffffffu, s, off);

    float beta = 1.f / (1.f + __expf(-s));
    float4 r;
    r.x = beta * sk.x + (1.f - beta) * o.x;
    r.y = beta * sk.y + (1.f - beta) * o.y;
    r.z = beta * sk.z + (1.f - beta) * o.z;
    r.w = beta * sk.w + (1.f - beta) * o.w;
    *(float4*)(out + (size_t)node * HC + lane * 4) = r;
}

// ---------------- launch ----------------
extern "C" void kernel_launch(void* const* d_in, const int* in_sizes, int n_in,
                              void* d_out, int out_size)
{
    const float* x         = (const float*)d_in[0];
    const float* edge_attr = (const float*)d_in[1];
    const int*   eidx      = (const int*)  d_in[2];
    const float* Wq = (const float*)d_in[3];
    const float* bq = (const float*)d_in[4];
    const float* Wk = (const float*)d_in[5];
    const float* bk = (const float*)d_in[6];
    const float* Wv = (const float*)d_in[7];
    const float* bv = (const float*)d_in[8];
    const float* We = (const float*)d_in[9];
    const float* Ws = (const float*)d_in[10];
    const float* bs = (const float*)d_in[11];
    const float* Wb = (const float*)d_in[12];
    float* out = (float*)d_out;

    const int n = in_sizes[0] / INC;        // 100000
    const int e = in_sizes[2] / 2;          // 1600000
    const int* row = eidx;                  // dst
    const int* col = eidx + e;              // src

    // side stream + events for graph-forked CSR build (created once; no device mem)
    static cudaStream_t s2 = 0;
    static cudaEvent_t evFork = 0, evJoin = 0;
    if (s2 == 0) {
        cudaStreamCreateWithFlags(&s2, cudaStreamNonBlocking);
        cudaEventCreateWithFlags(&evFork, cudaEventDisableTiming);
        cudaEventCreateWithFlags(&evJoin, cudaEventDisableTiming);
    }

    // fork: CSR build chain on s2, GEMM chain on main stream
    cudaEventRecord(evFork, 0);
    cudaStreamWaitEvent(s2, evFork, 0);

    zero_deg_kernel<<<(n + 255) / 256, 256, 0, s2>>>(n);
    hist_kernel<<<(e + 255) / 256, 256, 0, s2>>>(row, e);
    const int nb = (n + 1023) / 1024;
    scanA_kernel<<<nb, 1024, 0, s2>>>(n);
    scanB_kernel<<<1, 256, 0, s2>>>(nb);
    scanC_kernel<<<(n + 255) / 256, 256, 0, s2>>>(n, e);
    scatter_kernel<<<(e + 255) / 256, 256, 0, s2>>>(row, col, e);
    cudaEventRecord(evJoin, s2);

    const int cvt_items = n * (INC / 4) + 4 * (INC * HC / 4);
    convert_kernel<<<(cvt_items + 255) / 256, 256>>>(x, Wq, Wk, Wv, Ws, n);

    dim3 ggrid((n + 127) / 128, 1, 4);
    gemm_mma_kernel<<<ggrid, 512>>>(bq, bk, bv, bs, n);

    // join, then aggregate
    cudaStreamWaitEvent(0, evJoin, 0);
    agg_kernel<<<(n + 7) / 8, 256>>>(edge_attr, We, Wb, out, n);
}